// round 17
// baseline (speedup 1.0000x reference)
#include <cuda_runtime.h>
#include <cuda_fp16.h>
#include <math.h>
#include <cstdint>

// Problem constants
#define Bn  4
#define Ln  1024
#define En  1024
#define Hn  16
#define HDn 64
#define NT  33          // 2*CLIP+1
#define CLIPV 16
#define SCALEF 0.125f   // 1/sqrt(64)
#define LOG2E 1.4426950408889634f
#define QSCALE (SCALEF * LOG2E)

// Scratch (device globals; no allocation allowed)
__device__ __half gQ[Bn*Hn*Ln*HDn];   // [b][h][l][d] fp16 (SCALE*LOG2E folded)
__device__ __half gK[Bn*Hn*Ln*HDn];
__device__ __half gV[Bn*Hn*Ln*HDn];
__device__ __half gY[Bn*Ln*En];       // [b][l][e] fp16
__device__ __half gXq[Bn*Ln*En];      // fp16 inputs
__device__ __half gXk[Bn*Ln*En];
__device__ __half gXv[Bn*Ln*En];
__device__ __half gWq[En*En];         // fp16 weights (wq pre-scaled)
__device__ __half gWk[En*En];
__device__ __half gWv[En*En];
__device__ __half gWo[En*En];
__device__ float  gBq[En];            // bq pre-scaled

// ---------------------------------------------------------------------------
// helpers
// ---------------------------------------------------------------------------
__device__ __forceinline__ uint32_t packh2(float x, float y) {
    __half2 h = __floats2half2_rn(x, y);
    return *reinterpret_cast<uint32_t*>(&h);
}

__device__ __forceinline__ uint32_t h2exp2(uint32_t x) {
    uint32_t r;
    asm("ex2.approx.f16x2 %0, %1;" : "=r"(r) : "r"(x));
    return r;
}

__device__ __forceinline__ float2 h2unpack(uint32_t x) {
    __half2 h = *reinterpret_cast<__half2*>(&x);
    return __half22float2(h);
}

__device__ __forceinline__ uint32_t h2add(uint32_t a, uint32_t b) {
    __half2 ha = *reinterpret_cast<__half2*>(&a);
    __half2 hb = *reinterpret_cast<__half2*>(&b);
    __half2 hc = __hadd2(ha, hb);
    return *reinterpret_cast<uint32_t*>(&hc);
}

__device__ __forceinline__ void cp_async16(void* dst, const void* src) {
    uint32_t d = (uint32_t)__cvta_generic_to_shared(dst);
    asm volatile("cp.async.cg.shared.global [%0], [%1], 16;\n" :: "r"(d), "l"(src));
}

__device__ __forceinline__ void cp_async16_s(uint32_t dst, const void* src) {
    asm volatile("cp.async.cg.shared.global [%0], [%1], 16;\n" :: "r"(dst), "l"(src));
}

__device__ __forceinline__ void ldsm4(uint32_t& r0, uint32_t& r1,
                                      uint32_t& r2, uint32_t& r3, const void* p) {
    uint32_t a = (uint32_t)__cvta_generic_to_shared(p);
    asm volatile("ldmatrix.sync.aligned.m8n8.x4.shared.b16 {%0,%1,%2,%3}, [%4];"
                 : "=r"(r0), "=r"(r1), "=r"(r2), "=r"(r3) : "r"(a));
}

__device__ __forceinline__ void ldsm4_s(uint32_t& r0, uint32_t& r1,
                                        uint32_t& r2, uint32_t& r3, uint32_t a) {
    asm volatile("ldmatrix.sync.aligned.m8n8.x4.shared.b16 {%0,%1,%2,%3}, [%4];"
                 : "=r"(r0), "=r"(r1), "=r"(r2), "=r"(r3) : "r"(a));
}

__device__ __forceinline__ void ldsm4t(uint32_t& r0, uint32_t& r1,
                                       uint32_t& r2, uint32_t& r3, const void* p) {
    uint32_t a = (uint32_t)__cvta_generic_to_shared(p);
    asm volatile("ldmatrix.sync.aligned.m8n8.x4.trans.shared.b16 {%0,%1,%2,%3}, [%4];"
                 : "=r"(r0), "=r"(r1), "=r"(r2), "=r"(r3) : "r"(a));
}

__device__ __forceinline__ void mma_f16(float* d,
    uint32_t a0, uint32_t a1, uint32_t a2, uint32_t a3,
    uint32_t b0, uint32_t b1)
{
    asm volatile(
        "mma.sync.aligned.m16n8k16.row.col.f32.f16.f16.f32 "
        "{%0,%1,%2,%3}, {%4,%5,%6,%7}, {%8,%9}, {%0,%1,%2,%3};"
        : "+f"(d[0]), "+f"(d[1]), "+f"(d[2]), "+f"(d[3])
        : "r"(a0), "r"(a1), "r"(a2), "r"(a3), "r"(b0), "r"(b1));
}

__device__ __forceinline__ uint32_t sw128(uint32_t off) {
    return off ^ ((off >> 3) & 0x70);
}

// ---------------------------------------------------------------------------
// Flat grid-stride fp32 -> fp16 conversion of all 7 tensors (+ scaled bq).
// wq is pre-scaled by SCALE*LOG2E (Q is only ever consumed scaled).
// ---------------------------------------------------------------------------
#define NIN8 ((Bn*Ln*En)/8)   // 524288 units of 8 halves
#define NW8  ((En*En)/8)      // 131072

__global__ __launch_bounds__(256) void convert_all_kernel(
    const float* __restrict__ xq, const float* __restrict__ xk,
    const float* __restrict__ xv,
    const float* __restrict__ wq, const float* __restrict__ wk,
    const float* __restrict__ wv, const float* __restrict__ wo,
    const float* __restrict__ bq,
    __half* __restrict__ oxq, __half* __restrict__ oxk, __half* __restrict__ oxv,
    __half* __restrict__ owq, __half* __restrict__ owk,
    __half* __restrict__ owv, __half* __restrict__ owo,
    float* __restrict__ obq)
{
    if (blockIdx.x == 0) {
        // scale bq (1024 floats = 256 float4)
        float4 b = ((const float4*)bq)[threadIdx.x];
        b.x *= QSCALE; b.y *= QSCALE; b.z *= QSCALE; b.w *= QSCALE;
        ((float4*)obq)[threadIdx.x] = b;
    }
    const int total = 3 * NIN8 + 4 * NW8;
    int stride = gridDim.x * 256;
    for (int i = blockIdx.x * 256 + threadIdx.x; i < total; i += stride) {
        const float* src; __half* dst; int off; float sc = 1.f;
        if (i < NIN8)                 { src = xq; dst = oxq; off = i; }
        else if (i < 2 * NIN8)        { src = xk; dst = oxk; off = i - NIN8; }
        else if (i < 3 * NIN8)        { src = xv; dst = oxv; off = i - 2 * NIN8; }
        else if (i < 3 * NIN8 + NW8)  { src = wq; dst = owq; off = i - 3 * NIN8; sc = QSCALE; }
        else if (i < 3 * NIN8 + 2 * NW8) { src = wk; dst = owk; off = i - 3 * NIN8 - NW8; }
        else if (i < 3 * NIN8 + 3 * NW8) { src = wv; dst = owv; off = i - 3 * NIN8 - 2 * NW8; }
        else                          { src = wo; dst = owo; off = i - 3 * NIN8 - 3 * NW8; }
        float4 a = ((const float4*)src)[2 * off];
        float4 b = ((const float4*)src)[2 * off + 1];
        uint4 o;
        o.x = packh2(a.x * sc, a.y * sc); o.y = packh2(a.z * sc, a.w * sc);
        o.z = packh2(b.x * sc, b.y * sc); o.w = packh2(b.z * sc, b.w * sc);
        ((uint4*)dst)[off] = o;
    }
}

// ---------------------------------------------------------------------------
// fp16 tensor-core GEMM (unchanged — fully unrolled k-loop).
// ---------------------------------------------------------------------------
#define GTILE 16384                       // 128 rows * 128 bytes
#define GS_TOTAL (6 * GTILE)              // 3 stages * (A + B) = 96 KB

__device__ __forceinline__ void gemm_body(
    const __half* __restrict__ A, const __half* __restrict__ W,
    const float* __restrict__ bias, void* __restrict__ Cout, int head_layout)
{
    extern __shared__ char sm[];
    uint32_t smem = (uint32_t)__cvta_generic_to_shared(sm);
    uint32_t smA = smem, smB = smem + 3 * GTILE;
    const int Kd = 1024;

    int tid  = threadIdx.x;
    int warp = tid >> 5, lane = tid & 31;
    int wm = (warp >> 1) << 5;
    int wn = (warp & 1) << 6;
    int g = lane >> 2, c = lane & 3;
    int m0 = blockIdx.y << 7, n0 = blockIdx.x << 7;

    int lrow = (lane & 7) + ((lane >> 3) & 1) * 8;
    int lcol = (lane >> 4) * 8;

    int r = tid >> 1;
    int chbase = (tid & 1) * 4;
    const __half* Ag = A + (size_t)(m0 + r) * Kd;
    const __half* Wg = W + (size_t)(n0 + r) * Kd;

    float acc[2][8][4];
#pragma unroll
    for (int mi = 0; mi < 2; mi++)
#pragma unroll
        for (int ni = 0; ni < 8; ni++)
#pragma unroll
            for (int q = 0; q < 4; q++) acc[mi][ni][q] = 0.f;

    auto load_stage = [&](int s, int k0) {
#pragma unroll
        for (int q = 0; q < 4; q++) {
            int ch = chbase + q;
            uint32_t d = sw128((uint32_t)(r * 128 + ch * 16));
            cp_async16_s(smA + s * GTILE + d, Ag + k0 + ch * 8);
            cp_async16_s(smB + s * GTILE + d, Wg + k0 + ch * 8);
        }
    };

    load_stage(0, 0);
    asm volatile("cp.async.commit_group;\n");
    load_stage(1, 64);
    asm volatile("cp.async.commit_group;\n");

    const int NITER = Kd / 64;   // 16
#pragma unroll
    for (int t = 0; t < NITER; t++) {
        asm volatile("cp.async.wait_group 1;\n");
        __syncthreads();
        if (t + 2 < NITER) {
            load_stage((t + 2) % 3, (t + 2) * 64);
        }
        asm volatile("cp.async.commit_group;\n");

        const int s = t % 3;
#pragma unroll
        for (int ks = 0; ks < 4; ks++) {
            int kc = ks * 16 + lcol;
            uint32_t af[2][4], bf[4][4];
#pragma unroll
            for (int mi = 0; mi < 2; mi++) {
                uint32_t addr = smA + s * GTILE +
                    sw128((uint32_t)((wm + mi * 16 + lrow) * 128 + kc * 2));
                ldsm4_s(af[mi][0], af[mi][1], af[mi][2], af[mi][3], addr);
            }
#pragma unroll
            for (int p = 0; p < 4; p++) {
                uint32_t addr = smB + s * GTILE +
                    sw128((uint32_t)((wn + p * 16 + lrow) * 128 + kc * 2));
                ldsm4_s(bf[p][0], bf[p][1], bf[p][2], bf[p][3], addr);
            }
#pragma unroll
            for (int mi = 0; mi < 2; mi++)
#pragma unroll
                for (int ni = 0; ni < 8; ni++) {
                    int p = ni >> 1;
                    uint32_t b0 = (ni & 1) ? bf[p][1] : bf[p][0];
                    uint32_t b1 = (ni & 1) ? bf[p][3] : bf[p][2];
                    mma_f16(acc[mi][ni], af[mi][0], af[mi][1], af[mi][2], af[mi][3],
                            b0, b1);
                }
        }
    }

#pragma unroll
    for (int mi = 0; mi < 2; mi++) {
#pragma unroll
        for (int ni = 0; ni < 8; ni++) {
            int row = m0 + wm + (mi << 4) + g;
            int col = n0 + wn + (ni << 3) + (c << 1);
            float b0 = bias[col], b1 = bias[col + 1];
            float x0 = acc[mi][ni][0] + b0, x1 = acc[mi][ni][1] + b1;
            float x2 = acc[mi][ni][2] + b0, x3 = acc[mi][ni][3] + b1;
            if (head_layout) {
                __half* C = (__half*)Cout;
                int b = row >> 10, l = row & 1023, h = col >> 6, d = col & 63;
                size_t off = (((size_t)(b * Hn + h)) << 16) + ((size_t)l << 6) + d;
                *(uint32_t*)(C + off) = packh2(x0, x1);
                int row2 = row + 8;
                int b2 = row2 >> 10, l2 = row2 & 1023;
                size_t off2 = (((size_t)(b2 * Hn + h)) << 16) + ((size_t)l2 << 6) + d;
                *(uint32_t*)(C + off2) = packh2(x2, x3);
            } else {
                float* C = (float*)Cout;
                *(float2*)(C + (size_t)row * 1024 + col) = make_float2(x0, x1);
                *(float2*)(C + (size_t)(row + 8) * 1024 + col) = make_float2(x2, x3);
            }
        }
    }
}

__global__ __launch_bounds__(256, 2) void qkv_gemm_kernel(
    const __half* __restrict__ xq, const __half* __restrict__ xk,
    const __half* __restrict__ xv,
    const __half* __restrict__ wq, const __half* __restrict__ wk,
    const __half* __restrict__ wv,
    const float* __restrict__ bq, const float* __restrict__ bk,
    const float* __restrict__ bv,
    __half* __restrict__ Q, __half* __restrict__ K, __half* __restrict__ V)
{
    if (blockIdx.z == 0)      gemm_body(xq, wq, bq, Q, 1);
    else if (blockIdx.z == 1) gemm_body(xk, wk, bk, K, 1);
    else                      gemm_body(xv, wv, bv, V, 1);
}

__global__ __launch_bounds__(256, 2) void out_gemm_kernel(
    const __half* __restrict__ Y, const __half* __restrict__ wo,
    const float* __restrict__ bo, float* __restrict__ out)
{
    gemm_body(Y, wo, bo, out, 0);
}

// ---------------------------------------------------------------------------
// fp16 tensor-core flash attention (Q pre-scaled by SCALE*LOG2E upstream);
// Q tile via cp.async; log2-domain softmax, f16x2 exp, hoisted fragments,
// RQ + rel_v epilogue via MMA, warp-vote skips, atomic-free buckets.
// ---------------------------------------------------------------------------
#define QPAD 72

struct __align__(16) AttnSmem {
    __half Qs[128][QPAD];     // pre-scaled Q
    __half Ks[2][64][QPAD];   // [j][d]
    __half Vs[2][64][QPAD];   // [j][d]
    float RQs[128][NT];       // log2-domain bias
    float Wb[128][NT];
    __half relkh[48][QPAD];   // fp16 relk, rows 33..47 zero (MMA B operand)
    __half relvh[48][QPAD];   // fp16 relv, rows 33..47 zero (MMA B operand)
};

__device__ __forceinline__ void load_kv_tile(AttnSmem& s, int buf,
    const __half* Kb, const __half* Vb, int j0, int tid)
{
    int j = tid >> 2;
    int ch = (tid & 3) << 4;
    const __half* ks = Kb + (size_t)(j0 + j) * 64 + ch;
    const __half* vs = Vb + (size_t)(j0 + j) * 64 + ch;
    cp_async16(&s.Ks[buf][j][ch],     ks);
    cp_async16(&s.Ks[buf][j][ch + 8], ks + 8);
    cp_async16(&s.Vs[buf][j][ch],     vs);
    cp_async16(&s.Vs[buf][j][ch + 8], vs + 8);
}

__global__ __launch_bounds__(256, 2) void attn_kernel(
    const __half* __restrict__ Q, const __half* __restrict__ Kg,
    const __half* __restrict__ Vg, const float* __restrict__ relk,
    const float* __restrict__ relv, __half* __restrict__ Y)
{
    extern __shared__ char smem_raw[];
    AttnSmem& s = *reinterpret_cast<AttnSmem*>(smem_raw);
    int tid = threadIdx.x;
    int warp = tid >> 5, lane = tid & 31;
    int g = lane >> 2, c = lane & 3;
    int r0 = warp * 16 + g;
    int r1 = r0 + 8;
    int lrow = (lane & 7) + ((lane >> 3) & 1) * 8;
    int lcol = (lane >> 4) * 8;
    int vrow = (lane & 7) + (lane >> 4) * 8;
    int vcol = ((lane >> 3) & 1) * 8;

    int bh = blockIdx.y;
    int bx = blockIdx.x;
    int i0 = bx * 128;
    const __half* Qb = Q + ((size_t)bh << 16) + (size_t)i0 * 64;
    const __half* Kb = Kg + ((size_t)bh << 16);
    const __half* Vb = Vg + ((size_t)bh << 16);

    // KV tile 0 + Q tile, one commit group
    load_kv_tile(s, 0, Kb, Vb, 0, tid);
    {
        int r = tid >> 1;
        int ch = (tid & 1) * 32;
        const __half* src = Qb + (size_t)r * 64 + ch;
        cp_async16(&s.Qs[r][ch],      src);
        cp_async16(&s.Qs[r][ch + 8],  src + 8);
        cp_async16(&s.Qs[r][ch + 16], src + 16);
        cp_async16(&s.Qs[r][ch + 24], src + 24);
    }
    asm volatile("cp.async.commit_group;\n");

    for (int idx = tid; idx < 48 * 64; idx += 256) {
        int row = idx >> 6, col = idx & 63;
        bool valid = (row < NT);
        s.relkh[row][col] = valid ? __float2half(relk[row * 64 + col]) : __float2half(0.f);
        s.relvh[row][col] = valid ? __float2half(relv[row * 64 + col]) : __float2half(0.f);
    }
    for (int idx = tid; idx < 128 * NT; idx += 256)
        s.Wb[idx / NT][idx % NT] = 0.f;
    asm volatile("cp.async.wait_group 0;\n");   // Q + KV0 resident
    __syncthreads();

    // hoist Q fragments (loop-invariant across j-tiles)
    uint32_t aq[4][4];
#pragma unroll
    for (int ks = 0; ks < 4; ks++)
        ldsm4(aq[ks][0], aq[ks][1], aq[ks][2], aq[ks][3],
              &s.Qs[warp * 16 + lrow][ks * 16 + lcol]);

    // ---- RQ = Q @ relk^T via tensor cores (N padded to 48) ----
    {
        float rqf[6][4];
#pragma unroll
        for (int u = 0; u < 6; u++)
#pragma unroll
            for (int q = 0; q < 4; q++) rqf[u][q] = 0.f;
#pragma unroll
        for (int ks = 0; ks < 4; ks++) {
            int kc = ks * 16 + lcol;
#pragma unroll
            for (int p = 0; p < 3; p++) {
                uint32_t b0, b1, b2, b3;
                ldsm4(b0, b1, b2, b3, &s.relkh[p * 16 + lrow][kc]);
                mma_f16(rqf[2 * p],     aq[ks][0], aq[ks][1], aq[ks][2], aq[ks][3], b0, b2);
                mma_f16(rqf[2 * p + 1], aq[ks][0], aq[ks][1], aq[ks][2], aq[ks][3], b1, b3);
            }
        }
#pragma unroll
        for (int p = 0; p < 3; p++)
#pragma unroll
            for (int sub = 0; sub < 2; sub++)
#pragma unroll
                for (int e = 0; e < 2; e++) {
                    int t = p * 16 + sub * 8 + 2 * c + e;
                    if (t < NT) {
                        s.RQs[r0][t] = rqf[2 * p + sub][e];
                        s.RQs[r1][t] = rqf[2 * p + sub][2 + e];
                    }
                }
    }
    __syncthreads();   // RQs scatter visible to all threads
    // hoist far-tile biases (buckets 0 and 32) into registers
    float rqA0 = s.RQs[r0][0], rqA32 = s.RQs[r0][32];
    float rqB0 = s.RQs[r1][0], rqB32 = s.RQs[r1][32];

    float m0s = -1e30f, m1s = -1e30f;
    float l0 = 0.f, l1 = 0.f;
    float b0a = 0.f, b0b = 0.f, b32a = 0.f, b32b = 0.f;
    float mW0 = -1e30f, mW1 = -1e30f;
    float acc[8][4];
#pragma unroll
    for (int ni = 0; ni < 8; ni++)
#pragma unroll
        for (int q = 0; q < 4; q++) acc[ni][q] = 0.f;

    int ig0 = i0 + r0, ig1 = i0 + r1;

#pragma unroll 2
    for (int jt = 0; jt < 16; jt++) {
        int buf = jt & 1;
        int j0 = jt * 64;
        asm volatile("cp.async.wait_group 0;\n");
        __syncthreads();      // KV[buf] visible
        if (jt + 1 < 16)
            load_kv_tile(s, buf ^ 1, Kb, Vb, j0 + 64, tid);
        asm volatile("cp.async.commit_group;\n");

        int dj = jt - 2 * bx;
        bool far_left  = (dj <= -2);
        bool far_right = (dj >= 3);
        bool diag = !(far_left || far_right);

        // ---- S = Q K^T ----
        float sf[8][4];
#pragma unroll
        for (int ni = 0; ni < 8; ni++)
#pragma unroll
            for (int q = 0; q < 4; q++) sf[ni][q] = 0.f;
#pragma unroll
        for (int ks = 0; ks < 4; ks++) {
            int kc = ks * 16 + lcol;
#pragma unroll
            for (int p = 0; p < 4; p++) {
                uint32_t b0, b1, b2, b3;
                ldsm4(b0, b1, b2, b3, &s.Ks[buf][p * 16 + lrow][kc]);
                mma_f16(sf[2 * p],     aq[ks][0], aq[ks][1], aq[ks][2], aq[ks][3], b0, b2);
                mma_f16(sf[2 * p + 1], aq[ks][0], aq[ks][1], aq[ks][2], aq[ks][3], b1, b3);
            }
        }

        // ---- diag tiles: per-element bias before max ----
        if (diag) {
#pragma unroll
            for (int ni = 0; ni < 8; ni++) {
#pragma unroll
                for (int e = 0; e < 2; e++) {
                    int j = j0 + ni * 8 + 2 * c + e;
                    int d0 = j - ig0; d0 = d0 < -CLIPV ? -CLIPV : (d0 > CLIPV ? CLIPV : d0);
                    int d1 = j - ig1; d1 = d1 < -CLIPV ? -CLIPV : (d1 > CLIPV ? CLIPV : d1);
                    sf[ni][e]     += s.RQs[r0][d0 + CLIPV];
                    sf[ni][2 + e] += s.RQs[r1][d1 + CLIPV];
                }
            }
        }

        // ---- max reduction (raw for far tiles; bias folded as offset) ----
        float mt0 = -1e30f, mt1 = -1e30f;
#pragma unroll
        for (int ni = 0; ni < 8; ni++) {
            mt0 = fmaxf(mt0, fmaxf(sf[ni][0], sf[ni][1]));
            mt1 = fmaxf(mt1, fmaxf(sf[ni][2], sf[ni][3]));
        }
        mt0 = fmaxf(mt0, __shfl_xor_sync(0xffffffffu, mt0, 1));
        mt0 = fmaxf(mt0, __shfl_xor_sync(0xffffffffu, mt0, 2));
        mt1 = fmaxf(mt1, __shfl_xor_sync(0xffffffffu, mt1, 1));
        mt1 = fmaxf(mt1, __shfl_xor_sync(0xffffffffu, mt1, 2));

        float mn0, mn1, off0, off1;
        if (!diag) {
            float rq0 = far_left ? rqA0 : rqA32;
            float rq1 = far_left ? rqB0 : rqB32;
            mn0 = fmaxf(m0s, mt0 + rq0);
            mn1 = fmaxf(m1s, mt1 + rq1);
            off0 = mn0 - rq0; off1 = mn1 - rq1;
        } else {
            mn0 = fmaxf(m0s, mt0);
            mn1 = fmaxf(m1s, mt1);
            off0 = mn0; off1 = mn1;
        }

        // ---- warp-vote alpha skip ----
        bool nochg = (mn0 == m0s) && (mn1 == m1s);
        bool skip = __all_sync(0xffffffffu, nochg);
        float al0 = 1.f, al1 = 1.f;
        if (!skip) {
            al0 = exp2f(m0s - mn0);
            al1 = exp2f(m1s - mn1);
        }

        // ---- P = exp2(S - off) directly in fp16 fragments ----
        uint32_t ap[4][4];
#pragma unroll
        for (int kk = 0; kk < 4; kk++) {
            ap[kk][0] = h2exp2(packh2(sf[2 * kk][0] - off0,     sf[2 * kk][1] - off0));
            ap[kk][1] = h2exp2(packh2(sf[2 * kk][2] - off1,     sf[2 * kk][3] - off1));
            ap[kk][2] = h2exp2(packh2(sf[2 * kk + 1][0] - off0, sf[2 * kk + 1][1] - off0));
            ap[kk][3] = h2exp2(packh2(sf[2 * kk + 1][2] - off1, sf[2 * kk + 1][3] - off1));
        }

        // ---- row sums: one-level hadd2 pairing, then fp32 ----
        float rs0, rs1;
        {
            uint32_t h0 = h2add(ap[0][0], ap[0][2]);
            uint32_t h1 = h2add(ap[1][0], ap[1][2]);
            uint32_t h2 = h2add(ap[2][0], ap[2][2]);
            uint32_t h3 = h2add(ap[3][0], ap[3][2]);
            float2 f0 = h2unpack(h0), f1 = h2unpack(h1);
            float2 f2 = h2unpack(h2), f3 = h2unpack(h3);
            rs0 = ((f0.x + f0.y) + (f1.x + f1.y)) + ((f2.x + f2.y) + (f3.x + f3.y));
            uint32_t k0 = h2add(ap[0][1], ap[0][3]);
            uint32_t k1 = h2add(ap[1][1], ap[1][3]);
            uint32_t k2 = h2add(ap[2][1], ap[2][3]);
            uint32_t k3 = h2add(ap[3][1], ap[3][3]);
            float2 e0 = h2unpack(k0), e1 = h2unpack(k1);
            float2 e2 = h2unpack(k2), e3 = h2unpack(k3);
            rs1 = ((e0.x + e0.y) + (e1.x + e1.y)) + ((e2.x + e2.y) + (e3.x + e3.y));
        }
        rs0 += __shfl_xor_sync(0xffffffffu, rs0, 1);
        rs0 += __shfl_xor_sync(0xffffffffu, rs0, 2);
        rs1 += __shfl_xor_sync(0xffffffffu, rs1, 1);
        rs1 += __shfl_xor_sync(0xffffffffu, rs1, 2);
        if (skip) { l0 += rs0; l1 += rs1; }
        else      { l0 = l0 * al0 + rs0; l1 = l1 * al1 + rs1; }

        // ---- bucket weights ----
        if (far_left) {
            if (skip) { b0a += rs0; b0b += rs1; }
            else {
                b0a = b0a * al0 + rs0;  b0b = b0b * al1 + rs1;
                b32a *= al0;            b32b *= al1;
            }
        } else if (far_right) {
            if (skip) { b32a += rs0; b32b += rs1; }
            else {
                b32a = b32a * al0 + rs0; b32b = b32b * al1 + rs1;
                b0a *= al0;              b0b *= al1;
            }
        } else {
            // interior rescale — skipped when no row's diag reference changed
            bool wno = (mW0 == mn0) && (mW1 == mn1);
            if (!__all_sync(0xffffffffu, wno)) {
                float wsc0 = exp2f(mW0 - mn0);
                float wsc1 = exp2f(mW1 - mn1);
#pragma unroll
                for (int e = 0; e < 2; e++) {
                    int rr0 = (2 * c + e - ig0) & 7;
                    int rr1 = (2 * c + e - ig1) & 7;
#pragma unroll
                    for (int tt = 0; tt < 4; tt++) {
                        int t0 = rr0 + 8 * tt;
                        int t1 = rr1 + 8 * tt;
                        if (t0 >= 1) s.Wb[r0][t0] *= wsc0;
                        if (t1 >= 1) s.Wb[r1][t1] *= wsc1;
                    }
                }
            }
            float c0a = 0.f, c0b = 0.f, c32a = 0.f, c32b = 0.f;
#pragma unroll
            for (int kk = 0; kk < 4; kk++) {
#pragma unroll
                for (int sub = 0; sub < 2; sub++) {   // ni = 2kk+sub
                    int ni = 2 * kk + sub;
                    float2 p0 = h2unpack(ap[kk][2 * sub]);       // row r0
                    float2 p1 = h2unpack(ap[kk][2 * sub + 1]);   // row r1
                    int jb = j0 + ni * 8 + 2 * c;
                    int d0 = jb - ig0;
                    int d1 = jb - ig1;
                    if (d0 <= -CLIPV) c0a += p0.x;
                    else if (d0 >= CLIPV) c32a += p0.x;
                    else s.Wb[r0][d0 + CLIPV] += p0.x;
                    if (d0 + 1 <= -CLIPV) c0a += p0.y;
                    else if (d0 + 1 >= CLIPV) c32a += p0.y;
                    else s.Wb[r0][d0 + 1 + CLIPV] += p0.y;
                    if (d1 <= -CLIPV) c0b += p1.x;
                    else if (d1 >= CLIPV) c32b += p1.x;
                    else s.Wb[r1][d1 + CLIPV] += p1.x;
                    if (d1 + 1 <= -CLIPV) c0b += p1.y;
                    else if (d1 + 1 >= CLIPV) c32b += p1.y;
                    else s.Wb[r1][d1 + 1 + CLIPV] += p1.y;
                }
            }
            c0a += __shfl_xor_sync(0xffffffffu, c0a, 1);
            c0a += __shfl_xor_sync(0xffffffffu, c0a, 2);
            c0b += __shfl_xor_sync(0xffffffffu, c0b, 1);
            c0b += __shfl_xor_sync(0xffffffffu, c0b, 2);
            c32a += __shfl_xor_sync(0xffffffffu, c32a, 1);
            c32a += __shfl_xor_sync(0xffffffffu, c32a, 2);
            c32b += __shfl_xor_sync(0xffffffffu, c32b, 1);
            c32b += __shfl_xor_sync(0xffffffffu, c32b, 2);
            if (skip) {
                b0a += c0a;   b0b += c0b;
                b32a += c32a; b32b += c32b;
            } else {
                b0a = b0a * al0 + c0a;   b0b = b0b * al1 + c0b;
                b32a = b32a * al0 + c32a; b32b = b32b * al1 + c32b;
            }
            mW0 = mn0; mW1 = mn1;
        }
        m0s = mn0; m1s = mn1;

        // ---- acc = acc*alpha (skipped when max unchanged) + P @ V ----
        if (!skip) {
#pragma unroll
            for (int ni = 0; ni < 8; ni++) {
                acc[ni][0] *= al0; acc[ni][1] *= al0;
                acc[ni][2] *= al1; acc[ni][3] *= al1;
            }
        }
#pragma unroll
        for (int kk = 0; kk < 4; kk++) {
#pragma unroll
            for (int p = 0; p < 4; p++) {
                uint32_t b0, b1, b2, b3;
                ldsm4t(b0, b1, b2, b3, &s.Vs[buf][kk * 16 + vrow][p * 16 + vcol]);
                mma_f16(acc[2 * p],     ap[kk][0], ap[kk][1], ap[kk][2], ap[kk][3], b0, b2);
                mma_f16(acc[2 * p + 1], ap[kk][0], ap[kk][1], ap[kk][2], ap[kk][3], b1, b3);
            }
        }
    }

    // ---- finalize boundary buckets into smem ----
    if (c == 0) {
        s.Wb[r0][0] = b0a;  s.Wb[r0][32] = b32a;
        s.Wb[r1][0] = b0b;  s.Wb[r1][32] = b32b;
    }
    __syncthreads();   // all bucket writes (scatter + boundary) visible

    // ---- rel_v epilogue via MMA: acc += W' @ relv (K=48 padded) ----
    {
        float ws0 = exp2f(mW0 - m0s);   // interior-bucket rescale to final max
        float ws1 = exp2f(mW1 - m1s);
        uint32_t aw[3][4];
#pragma unroll
        for (int kk = 0; kk < 3; kk++) {
#pragma unroll
            for (int half = 0; half < 2; half++) {
                int t0 = 16 * kk + 8 * half + 2 * c;
                int t1 = t0 + 1;
                float w0a = (t0 < NT) ? s.Wb[r0][t0] : 0.f;
                float w0b = (t1 < NT) ? s.Wb[r0][t1] : 0.f;
                float w1a = (t0 < NT) ? s.Wb[r1][t0] : 0.f;
                float w1b = (t1 < NT) ? s.Wb[r1][t1] : 0.f;
                if (t0 != 0 && t0 != 32) { w0a *= ws0; w1a *= ws1; }
                if (t1 != 0 && t1 != 32) { w0b *= ws0; w1b *= ws1; }
                aw[kk][half ? 2 : 0] = packh2(w0a, w0b);   // row r0
                aw[kk][half ? 3 : 1] = packh2(w1a, w1b);   // row r1
            }
        }
#pragma unroll
        for (int kk = 0; kk < 3; kk++) {
#pragma unroll
            for (int p = 0; p < 4; p++) {
                uint32_t b0, b1, b2, b3;
                ldsm4t(b0, b1, b2, b3, &s.relvh[kk * 16 + vrow][p * 16 + vcol]);
                mma_f16(acc[2 * p],     aw[kk][0], aw[kk][1], aw[kk][2], aw[kk][3], b0, b2);
                mma_f16(acc[2 * p + 1], aw[kk][0], aw[kk][1], aw[kk][2], aw[kk][3], b1, b3);
            }
        }
    }

    // ---- normalize and store ----
    {
        float li0 = 1.f / l0, li1 = 1.f / l1;
        int bb = bh >> 4, hh = bh & 15;
        __half* y0 = Y + ((size_t)(bb * 1024 + i0 + r0)) * 1024 + hh * 64;
        __half* y1 = Y + ((size_t)(bb * 1024 + i0 + r1)) * 1024 + hh * 64;
#pragma unroll
        for (int ni = 0; ni < 8; ni++) {
            int col = ni * 8 + 2 * c;
            *(uint32_t*)(y0 + col) = packh2(acc[ni][0] * li0, acc[ni][1] * li0);
            *(uint32_t*)(y1 + col) = packh2(acc[ni][2] * li1, acc[ni][3] * li1);
        }
    }
}

// ---------------------------------------------------------------------------

extern "C" void kernel_launch(void* const* d_in, const int* in_sizes, int n_in,
                              void* d_out, int out_size)
{
    const float* query = (const float*)d_in[0];
    const float* key   = (const float*)d_in[1];
    const float* value = (const float*)d_in[2];
    const float* wq = (const float*)d_in[3];
    const float* bq = (const float*)d_in[4];
    const float* wk = (const float*)d_in[5];
    const float* bk = (const float*)d_in[6];
    const float* wv = (const float*)d_in[7];
    const float* bv = (const float*)d_in[8];
    const float* wo = (const float*)d_in[9];
    const float* bo = (const float*)d_in[10];
    const float* relk = (const float*)d_in[11];
    const float* relv = (const float*)d_in[12];
    float* out = (float*)d_out;

    __half *Qp, *Kp, *Vp, *Yp, *Xq, *Xk, *Xv, *Wq, *Wk, *Wv, *Wo;
    float *Bq;
    cudaGetSymbolAddress((void**)&Qp, gQ);
    cudaGetSymbolAddress((void**)&Kp, gK);
    cudaGetSymbolAddress((void**)&Vp, gV);
    cudaGetSymbolAddress((void**)&Yp, gY);
    cudaGetSymbolAddress((void**)&Xq, gXq);
    cudaGetSymbolAddress((void**)&Xk, gXk);
    cudaGetSymbolAddress((void**)&Xv, gXv);
    cudaGetSymbolAddress((void**)&Wq, gWq);
    cudaGetSymbolAddress((void**)&Wk, gWk);
    cudaGetSymbolAddress((void**)&Wv, gWv);
    cudaGetSymbolAddress((void**)&Wo, gWo);
    cudaGetSymbolAddress((void**)&Bq, gBq);

    convert_all_kernel<<<592, 256>>>(query, key, value, wq, wk, wv, wo, bq,
                                     Xq, Xk, Xv, Wq, Wk, Wv, Wo, Bq);

    cudaFuncSetAttribute(qkv_gemm_kernel, cudaFuncAttributeMaxDynamicSharedMemorySize,
                         GS_TOTAL);
    cudaFuncSetAttribute(out_gemm_kernel, cudaFuncAttributeMaxDynamicSharedMemorySize,
                         GS_TOTAL);
    cudaFuncSetAttribute(attn_kernel, cudaFuncAttributeMaxDynamicSharedMemorySize,
                         (int)sizeof(AttnSmem));

    qkv_gemm_kernel<<<dim3(8, 32, 3), 256, GS_TOTAL>>>(Xq, Xk, Xv, Wq, Wk, Wv,
                                                       Bq, bk, bv, Qp, Kp, Vp);

    attn_kernel<<<dim3(8, 64), 256, sizeof(AttnSmem)>>>(Qp, Kp, Vp, relk, relv, Yp);

    out_gemm_kernel<<<dim3(8, 32), 256, GS_TOTAL>>>(Yp, Wo, bo, out);
}